// round 17
// baseline (speedup 1.0000x reference)
#include <cuda_runtime.h>
#include <cuda_fp16.h>
#include <math.h>
#include <math_constants.h>
#include <stdint.h>

#define B_   2
#define T_   1024
#define D_   512
#define H_   8
#define DK_  64
#define DFF_ 2048
#define L_   6
#define V_   50257
#define VP_  50304
#define PAD_ 50256
#define BT_  (B_*T_)
#define QKVW_ (3*D_)

// ---------------- scratch ----------------
__device__ float g_x[BT_*D_];
__device__ float g_v[BT_*D_];
__device__ float g_tmp[BT_*D_];

__device__ uint32_t g_xH[BT_*256];
__device__ uint32_t g_cH[BT_*256];
__device__ uint32_t g_fH[BT_*1024];
__device__ uint32_t g_qkpH[BT_*512];
__device__ uint32_t g_wqkvH[L_*QKVW_*256];
__device__ uint32_t g_woH[L_*D_*256];
__device__ uint32_t g_fc1H[L_*DFF_*256];
__device__ uint32_t g_fc2H[L_*D_*1024];
__device__ uint32_t g_lmhH[(size_t)VP_*256];

// ---------------- helpers ----------------
__device__ __forceinline__ uint32_t hpack1(float x0, float x1) {
    return ((uint32_t)__half_as_ushort(__float2half_rn(x1)) << 16)
         |  (uint32_t)__half_as_ushort(__float2half_rn(x0));
}

__device__ __forceinline__ float fexp(float x) {
    x = fmaxf(x, -87.0f);
    float t = fmaf(x, 1.4426950408889634f, 12582912.0f);
    float r = t - 12582912.0f;
    float f = fmaf(x, 1.4426950408889634f, -r);
    float p =        1.3333558e-3f;
    p = fmaf(p, f, 9.6181291e-3f);
    p = fmaf(p, f, 5.5504109e-2f);
    p = fmaf(p, f, 2.4022651e-1f);
    p = fmaf(p, f, 6.9314718e-1f);
    p = fmaf(p, f, 1.0f);
    int e = (__float_as_int(t) + 127) << 23;
    return p * __int_as_float(e);
}

#define MMA16(cc, a, b) \
    asm volatile("mma.sync.aligned.m16n8k16.row.col.f32.f16.f16.f32 " \
        "{%0,%1,%2,%3}, {%4,%5,%6,%7}, {%8,%9}, {%0,%1,%2,%3};" \
        : "+f"((cc)[0]), "+f"((cc)[1]), "+f"((cc)[2]), "+f"((cc)[3]) \
        : "r"((a)[0]), "r"((a)[1]), "r"((a)[2]), "r"((a)[3]), \
          "r"((b)[0]), "r"((b)[1]))

#define LDSM_X4(r0, r1, r2, r3, addr) \
    asm volatile("ldmatrix.sync.aligned.m8n8.x4.shared.b16 {%0,%1,%2,%3}, [%4];" \
        : "=r"(r0), "=r"(r1), "=r"(r2), "=r"(r3) : "r"(addr))

__device__ __forceinline__ void cpa16(uint32_t dst, const void* src) {
    asm volatile("cp.async.cg.shared.global [%0], [%1], 16;" :: "r"(dst), "l"(src));
}
#define CP_COMMIT() asm volatile("cp.async.commit_group;" ::: "memory")

// ================ prepack kernels (coalesced transpose, hi-only) ===============
__global__ void prepack_b_hi(const float* __restrict__ W, uint32_t* __restrict__ oH,
                             int K, int N, int Npad) {
    __shared__ uint32_t sh[64*33];
    const int KP = K >> 1;
    const int n0 = blockIdx.x * 64, kp0 = blockIdx.y * 32;
    const int tid = threadIdx.x;
    #pragma unroll
    for (int i = 0; i < 8; i++) {
        int f = tid + i*256;
        int n = f & 63, kp = f >> 6;
        int gn = n0 + n;
        float x0 = 0.f, x1 = 0.f;
        if (gn < N) {
            int k2 = (kp0 + kp) * 2;
            x0 = W[(size_t)k2*N + gn];
            x1 = W[(size_t)(k2 + 1)*N + gn];
        }
        sh[n*33 + kp] = hpack1(x0, x1);
    }
    __syncthreads();
    #pragma unroll
    for (int i = 0; i < 8; i++) {
        int f = tid + i*256;
        int kp = f & 31, n = f >> 5;
        oH[(size_t)(n0 + n)*KP + kp0 + kp] = sh[n*33 + kp];
    }
}

__global__ void prepack_qkvw(const float* __restrict__ WQ,
                             const float* __restrict__ WK,
                             const float* __restrict__ WV) {
    __shared__ uint32_t sh[64*33];
    const int l = blockIdx.z;
    const int n0 = blockIdx.x*64, kp0 = blockIdx.y*32;
    const int tid = threadIdx.x;
    #pragma unroll
    for (int i = 0; i < 8; i++) {
        int f = tid + i*256;
        int n = f & 63, kp = f >> 6;
        int gn = n0 + n;
        int part = gn >> 9, hh = (gn >> 6) & 7, kk = gn & 63;
        const float* W = part == 0 ? WQ : (part == 1 ? WK : WV);
        size_t base = (((size_t)l*H_ + hh)*D_ + 2*(kp0 + kp))*DK_ + kk;
        sh[n*33 + kp] = hpack1(W[base], W[base + DK_]);
    }
    __syncthreads();
    #pragma unroll
    for (int i = 0; i < 8; i++) {
        int f = tid + i*256;
        int kp = f & 31, n = f >> 5;
        g_wqkvH[(size_t)l*QKVW_*256 + (size_t)(n0 + n)*256 + kp0 + kp] = sh[n*33 + kp];
    }
}

__global__ void prepack_small(const float* __restrict__ WO,
                              const float* __restrict__ F1,
                              const float* __restrict__ F2) {
    __shared__ uint32_t sh[64*33];
    const int z = blockIdx.z;
    const int type = z / L_, l = z % L_;
    int K, N; const float* W; uint32_t* oH;
    if (type == 0)      { K = D_;   N = D_;   W = WO + (size_t)l*D_*D_;   oH = g_woH  + (size_t)l*D_*256; }
    else if (type == 1) { K = D_;   N = DFF_; W = F1 + (size_t)l*D_*DFF_; oH = g_fc1H + (size_t)l*DFF_*256; }
    else                { K = DFF_; N = D_;   W = F2 + (size_t)l*DFF_*D_; oH = g_fc2H + (size_t)l*D_*1024; }
    const int KP = K >> 1;
    const int n0 = blockIdx.x*64, kp0 = blockIdx.y*32;
    if (n0 >= N || kp0 >= KP) return;
    const int tid = threadIdx.x;
    #pragma unroll
    for (int i = 0; i < 8; i++) {
        int f = tid + i*256;
        int n = f & 63, kp = f >> 6;
        int k2 = (kp0 + kp)*2;
        sh[n*33 + kp] = hpack1(W[(size_t)k2*N + n0 + n], W[(size_t)(k2+1)*N + n0 + n]);
    }
    __syncthreads();
    #pragma unroll
    for (int i = 0; i < 8; i++) {
        int f = tid + i*256;
        int kp = f & 31, n = f >> 5;
        oH[(size_t)(n0 + n)*KP + kp0 + kp] = sh[n*33 + kp];
    }
}

// ========= single-pass fp16 mma.sync GEMM, 4-stage cp.async + ldmatrix =========
// OUT: 0 fp32 C, 1 packed, 2 qkv-mode. SWAP: grid dims swapped for L2 B-reuse.
#define AU 20
#define NST 4

template<int OUT, int EPI, bool GUARD, int NI, bool SWAP>
__global__ void __launch_bounds__(256, 2)
gemm_pk(int M, int N, int K,
        const uint32_t* __restrict__ aH,
        const uint32_t* __restrict__ bH,
        float* __restrict__ C, int ldc,
        uint32_t* __restrict__ oH,
        const float* __restrict__ bias)
{
    constexpr int NTILE = 32*NI;
    extern __shared__ uint32_t su[];
    const uint32_t sb = (uint32_t)__cvta_generic_to_shared(su);
    const uint32_t sbAH = sb;
    const uint32_t sbBH = sb + NST*128*AU*4;

    const int KP   = K >> 1;
    const int tid  = threadIdx.x;
    const int wid  = tid >> 5, lane = tid & 31;
    const int g    = lane >> 2, t = lane & 3;
    const int bm   = (SWAP ? blockIdx.x : blockIdx.y) * 128;
    const int bn   = (SWAP ? blockIdx.y : blockIdx.x) * NTILE;
    const int m0   = (wid >> 2) * 64, n0 = (wid & 3) * (8*NI);

    const int lane15 = lane & 15;
    const uint32_t aoff = (uint32_t)(lane15*AU + ((lane & 16) ? 4 : 0))*4;
    const int lbn = (lane & 7) + ((lane & 16) ? 8 : 0);
    const uint32_t boff = (uint32_t)(lbn*AU + ((lane & 8) ? 4 : 0))*4;

    float c[4][NI][4];
    #pragma unroll
    for (int mi = 0; mi < 4; mi++)
        #pragma unroll
        for (int ni = 0; ni < NI; ni++)
            #pragma unroll
            for (int j = 0; j < 4; j++) c[mi][ni][j] = 0.f;

    const int NKT = K >> 5;

    auto load_tile = [&](int kt, int st) {
        const int kp0 = kt << 4;
        #pragma unroll
        for (int i = 0; i < 2; i++) {
            int f = tid + i*256;
            int r = f >> 2, cc = (f & 3) << 2;
            size_t go = (size_t)(bm + r)*KP + kp0 + cc;
            cpa16(sbAH + (uint32_t)((st*128 + r)*AU + cc)*4, aH + go);
        }
        #pragma unroll
        for (int i = 0; i < NI/2; i++) {
            int f = tid + i*256;
            int n = f >> 2, cc = (f & 3) << 2;
            size_t go = (size_t)(bn + n)*KP + kp0 + cc;
            cpa16(sbBH + (uint32_t)((st*NTILE + n)*AU + cc)*4, bH + go);
        }
        CP_COMMIT();
    };

    // prologue: fill NST-1 = 3 stages (NKT >= 16 always here)
    load_tile(0, 0);
    load_tile(1, 1);
    load_tile(2, 2);

    for (int kt = 0; kt < NKT; kt++) {
        const int st = kt % NST;
        // wait until tile kt complete: pending = min(3, NKT-kt) groups at entry
        if (kt <= NKT - 3) {
            asm volatile("cp.async.wait_group 2;" ::: "memory");
        } else if (kt == NKT - 2) {
            asm volatile("cp.async.wait_group 1;" ::: "memory");
        } else {
            asm volatile("cp.async.wait_group 0;" ::: "memory");
        }
        __syncthreads();

        if (kt + NST - 1 < NKT)
            load_tile(kt + NST - 1, (kt + NST - 1) % NST);

        const uint32_t aHb = sbAH + (uint32_t)(st*128*AU)*4;
        const uint32_t bHb = sbBH + (uint32_t)(st*NTILE*AU)*4;

        #pragma unroll
        for (int ks = 0; ks < 2; ks++) {
            const int kb = ks*8;
            uint32_t bh[NI][2];
            #pragma unroll
            for (int np = 0; np < NI/2; np++) {
                LDSM_X4(bh[2*np][0], bh[2*np][1], bh[2*np+1][0], bh[2*np+1][1],
                        bHb + (uint32_t)((n0 + np*16)*AU + kb)*4 + boff);
            }
            #pragma unroll
            for (int mi = 0; mi < 4; mi++) {
                uint32_t ah[4];
                LDSM_X4(ah[0], ah[1], ah[2], ah[3],
                        aHb + (uint32_t)((m0 + mi*16)*AU + kb)*4 + aoff);
                #pragma unroll
                for (int ni = 0; ni < NI; ni++)
                    MMA16(c[mi][ni], ah, bh[ni]);
            }
        }
    }

    const int KP2 = (OUT == 2) ? 512 : (N >> 1);
    #pragma unroll
    for (int mi = 0; mi < 4; mi++) {
        const int r0 = bm + m0 + mi*16 + g;
        #pragma unroll
        for (int ni = 0; ni < NI; ni++) {
            const int c0 = bn + n0 + ni*8 + t*2;
            #pragma unroll
            for (int half = 0; half < 2; half++) {
                const int gr = r0 + half*8;
                float v0 = c[mi][ni][2*half + 0];
                float v1 = c[mi][ni][2*half + 1];
                if (EPI >= 1) { v0 += bias[c0]; v1 += bias[c0 + 1]; }
                if (EPI == 2) {
                    v0 = 0.5f*v0*(1.f + erff(v0*0.70710678118654752f));
                    v1 = 0.5f*v1*(1.f + erff(v1*0.70710678118654752f));
                }
                if (OUT == 0) {
                    if (!GUARD || c0 < N)     C[(size_t)gr*ldc + c0]     = v0;
                    if (!GUARD || c0 + 1 < N) C[(size_t)gr*ldc + c0 + 1] = v1;
                } else if (OUT == 1) {
                    oH[(size_t)gr*KP2 + (c0 >> 1)] = hpack1(v0, v1);
                } else {
                    if (c0 < 1024) {
                        oH[(size_t)gr*512 + (c0 >> 1)] = hpack1(v0, v1);
                    } else {
                        C[(size_t)gr*512 + (c0 - 1024)]     = v0;
                        C[(size_t)gr*512 + (c0 - 1024) + 1] = v1;
                    }
                }
            }
        }
    }
}

// ---------------- embedding ----------------
__global__ void embed_kernel(const int* __restrict__ ids,
                             const float* __restrict__ tok,
                             const float* __restrict__ pos) {
    const int row = blockIdx.x;
    const int t   = row % T_;
    const int id  = ids[row];
    const int tid = threadIdx.x;
    const float sc = 22.62741699796952f;
    const int d = tid*2;
    float e0 = (id == PAD_) ? 0.f : tok[(size_t)id*D_ + d];
    float e1 = (id == PAD_) ? 0.f : tok[(size_t)id*D_ + d + 1];
    float v0 = e0*sc + pos[(size_t)t*D_ + d];
    float v1 = e1*sc + pos[(size_t)t*D_ + d + 1];
    *reinterpret_cast<float2*>(g_x + (size_t)row*D_ + d) = make_float2(v0, v1);
    g_xH[row*256 + tid] = hpack1(v0, v1);
}

// ================ fattn2: single-fp16 flash attention (unpaired tiles) =========
#define FA2_SMEM (3*2304*4)

__global__ void __launch_bounds__(128) fattn2_kernel() {
    extern __shared__ uint32_t fsm[];
    uint32_t* VH = fsm + 2*2304;
    const uint32_t sbase = (uint32_t)__cvta_generic_to_shared(fsm);

    const int qb = blockIdx.x;          // 0..15 (one tile per CTA)
    const int bh = blockIdx.y;
    const int b = bh >> 3, h = bh & 7;
    const int tid = threadIdx.x;

    const int w = tid >> 5, lane = tid & 31;
    const int g = lane >> 2, t = lane & 3;
    const int mr = w*16;
    const uint32_t sQH = sbase;
    const uint32_t sKH = sbase + 9216, sVH = sbase + 18432;

    const int lane15 = lane & 15;
    const uint32_t qoff = (uint32_t)(lane15*36 + ((lane & 16) ? 4 : 0))*4;
    const int lbn = (lane & 7) + ((lane & 16) ? 8 : 0);
    const uint32_t koff = (uint32_t)(lbn*36 + ((lane & 8) ? 4 : 0))*4;

    #pragma unroll
    for (int i = 0; i < 4; i++) {
        int idx = tid + i*128;
        int r = idx >> 3, c4 = (idx & 7) << 2;
        size_t go = ((size_t)(b*1024 + qb*64 + r) << 9) + h*32 + c4;
        cpa16(sQH + (uint32_t)(r*36 + c4)*4, g_qkpH + go);
    }
    CP_COMMIT();

    float m0 = -CUDART_INF_F, m1 = -CUDART_INF_F, l0 = 0.f, l1 = 0.f;
    float o[8][4];
    #pragma unroll
    for (int nb = 0; nb < 8; nb++)
        #pragma unroll
        for (int j = 0; j < 4; j++) o[nb][j] = 0.f;

    const int nkt = qb + 1;
    for (int kt = 0; kt < nkt; kt++) {
        __syncthreads();
        #pragma unroll
        for (int i = 0; i < 4; i++) {
            int idx = tid + i*128;
            int r = idx >> 3, c4 = (idx & 7) << 2;
            size_t go = ((size_t)(b*1024 + kt*64 + r) << 9) + 256 + h*32 + c4;
            cpa16(sKH + (uint32_t)(r*36 + c4)*4, g_qkpH + go);
        }
        CP_COMMIT();
        #pragma unroll
        for (int i = 0; i < 16; i++) {
            int idx = tid + i*128;
            int n = idx & 63, r = idx >> 6;
            size_t base = ((size_t)(b*1024 + kt*64 + 2*r) << 9) + h*64 + n;
            VH[n*36 + r] = hpack1(g_v[base], g_v[base + 512]);
        }
        asm volatile("cp.async.wait_group 0;" ::: "memory");
        __syncthreads();

        // ---- S = Q K^T ----
        float sc[8][4];
        #pragma unroll
        for (int ni = 0; ni < 8; ni++)
            #pragma unroll
            for (int j = 0; j < 4; j++) sc[ni][j] = 0.f;
        #pragma unroll
        for (int j = 0; j < 4; j++) {
            uint32_t ah[4];
            LDSM_X4(ah[0], ah[1], ah[2], ah[3], sQH + (uint32_t)(mr*36 + j*8)*4 + qoff);
            uint32_t kf[8][2];
            #pragma unroll
            for (int np = 0; np < 4; np++) {
                LDSM_X4(kf[2*np][0], kf[2*np][1], kf[2*np+1][0], kf[2*np+1][1],
                        sKH + (uint32_t)(np*16*36 + j*8)*4 + koff);
            }
            #pragma unroll
            for (int ni = 0; ni < 8; ni++)
                MMA16(sc[ni], ah, kf[ni]);
        }
        const int qr0 = qb*64 + mr + g;
        const bool diag = (kt == qb);
        #pragma unroll
        for (int ni = 0; ni < 8; ni++)
            #pragma unroll
            for (int cc = 0; cc < 4; cc++) {
                float v = sc[ni][cc]*0.125f;
                if (diag) {
                    int key = kt*64 + ni*8 + 2*t + (cc & 1);
                    int qr = qr0 + (cc >> 1)*8;
                    if (key > qr) v = -CUDART_INF_F;
                }
                sc[ni][cc] = v;
            }

        float mx0 = -CUDART_INF_F, mx1 = -CUDART_INF_F;
        #pragma unroll
        for (int ni = 0; ni < 8; ni++) {
            mx0 = fmaxf(mx0, fmaxf(sc[ni][0], sc[ni][1]));
            mx1 = fmaxf(mx1, fmaxf(sc[ni][2], sc[ni][3]));
        }
        mx0 = fmaxf(mx0, __shfl_xor_sync(0xffffffffu, mx0, 1));
        mx0 = fmaxf(mx0, __shfl_xor_sync(0xffffffffu, mx0, 2));
        mx1 = fmaxf(mx1, __shfl_xor_sync(0xffffffffu, mx1, 1));
        mx1 = fmaxf(mx1, __shfl_xor_sync(0xffffffffu, mx1, 2));
        const float mn0 = fmaxf(m0, mx0), mn1 = fmaxf(m1, mx1);
        const float cr0 = fexp(m0 - mn0),  cr1 = fexp(m1 - mn1);
        float s0 = 0.f, s1 = 0.f;
        #pragma unroll
        for (int ni = 0; ni < 8; ni++) {
            float p0 = fexp(sc[ni][0] - mn0);
            float p1 = fexp(sc[ni][1] - mn0);
            float p2 = fexp(sc[ni][2] - mn1);
            float p3 = fexp(sc[ni][3] - mn1);
            sc[ni][0] = p0; sc[ni][1] = p1; sc[ni][2] = p2; sc[ni][3] = p3;
            s0 += p0 + p1; s1 += p2 + p3;
        }
        s0 += __shfl_xor_sync(0xffffffffu, s0, 1);
        s0 += __shfl_xor_sync(0xffffffffu, s0, 2);
        s1 += __shfl_xor_sync(0xffffffffu, s1, 1);
        s1 += __shfl_xor_sync(0xffffffffu, s1, 2);
        l0 = l0*cr0 + s0; l1 = l1*cr1 + s1;
        m0 = mn0; m1 = mn1;
        #pragma unroll
        for (int nb = 0; nb < 8; nb++) {
            o[nb][0] *= cr0; o[nb][1] *= cr0;
            o[nb][2] *= cr1; o[nb][3] *= cr1;
        }

        // ---- O += P V ----
        #pragma unroll
        for (int jj = 0; jj < 4; jj++) {
            uint32_t ah[4];
            ah[0] = hpack1(sc[2*jj][0],   sc[2*jj][1]);
            ah[1] = hpack1(sc[2*jj][2],   sc[2*jj][3]);
            ah[2] = hpack1(sc[2*jj+1][0], sc[2*jj+1][1]);
            ah[3] = hpack1(sc[2*jj+1][2], sc[2*jj+1][3]);
            uint32_t vf[8][2];
            #pragma unroll
            for (int np = 0; np < 4; np++) {
                LDSM_X4(vf[2*np][0], vf[2*np][1], vf[2*np+1][0], vf[2*np+1][1],
                        sVH + (uint32_t)(np*16*36 + jj*8)*4 + koff);
            }
            #pragma unroll
            for (int nb = 0; nb < 8; nb++)
                MMA16(o[nb], ah, vf[nb]);
        }
    }

    const float inv0 = 1.f / l0, inv1 = 1.f / l1;
    const int gr0 = b*1024 + qb*64 + mr + g;
    #pragma unroll
    for (int nb = 0; nb < 8; nb++) {
        const int kp = h*32 + nb*4 + t;
        g_cH[gr0*256 + kp]       = hpack1(o[nb][0]*inv0, o[nb][1]*inv0);
        g_cH[(gr0 + 8)*256 + kp] = hpack1(o[nb][2]*inv1, o[nb][3]*inv1);
    }
}

// ------------- fused residual add + LayerNorm -> fp32 x AND packed x -----------
__global__ void __launch_bounds__(256) add_ln_kernel(const float* __restrict__ g,
                                                     const float* __restrict__ bta) {
    const int row = blockIdx.x;
    float* x = g_x + (size_t)row*D_;
    const float* dl = g_tmp + (size_t)row*D_;
    const int tid = threadIdx.x;
    __shared__ float red[256];

    float2 xv = reinterpret_cast<const float2*>(x)[tid];
    float2 dv = reinterpret_cast<const float2*>(dl)[tid];
    float v0 = xv.x + dv.x;
    float v1 = xv.y + dv.y;

    red[tid] = v0 + v1; __syncthreads();
    for (int off = 128; off > 0; off >>= 1) {
        if (tid < off) red[tid] += red[tid + off];
        __syncthreads();
    }
    const float mu = red[0] * (1.f/512.f); __syncthreads();

    float d0 = v0 - mu, d1 = v1 - mu;
    red[tid] = d0*d0 + d1*d1; __syncthreads();
    for (int off = 128; off > 0; off >>= 1) {
        if (tid < off) red[tid] += red[tid + off];
        __syncthreads();
    }
    const float inv = rsqrtf(red[0]*(1.f/512.f) + 1e-5f);

    const int d = tid*2;
    float o0 = d0*inv*g[d]     + bta[d];
    float o1 = d1*inv*g[d + 1] + bta[d + 1];
    reinterpret_cast<float2*>(x)[tid] = make_float2(o0, o1);
    g_xH[row*256 + tid] = hpack1(o0, o1);
}

// ---------------- launch ----------------
#define SMEM_NI4 (NST*(128*AU + 128*AU)*4)   // 81920
#define SMEM_NI2 (NST*(128*AU + 64*AU)*4)    // 61440

extern "C" void kernel_launch(void* const* d_in, const int* in_sizes, int n_in,
                              void* d_out, int out_size) {
    const int*   ids  = (const int*)  d_in[0];
    const float* tok  = (const float*)d_in[1];
    const float* pos  = (const float*)d_in[2];
    const float* WQ   = (const float*)d_in[3];
    const float* WK   = (const float*)d_in[4];
    const float* WV   = (const float*)d_in[5];
    const float* WO   = (const float*)d_in[6];
    const float* ln1g = (const float*)d_in[7];
    const float* ln1b = (const float*)d_in[8];
    const float* fc1w = (const float*)d_in[9];
    const float* fc1b = (const float*)d_in[10];
    const float* fc2w = (const float*)d_in[11];
    const float* fc2b = (const float*)d_in[12];
    const float* ln2g = (const float*)d_in[13];
    const float* ln2b = (const float*)d_in[14];
    const float* lmh  = (const float*)d_in[15];
    float* out = (float*)d_out;

    float *pv, *ptmp;
    cudaGetSymbolAddress((void**)&pv,   g_v);
    cudaGetSymbolAddress((void**)&ptmp, g_tmp);

    uint32_t *xH, *cH, *fH, *qpH, *qkH, *woH, *f1H, *f2H, *lmH;
    cudaGetSymbolAddress((void**)&xH,  g_xH);
    cudaGetSymbolAddress((void**)&cH,  g_cH);
    cudaGetSymbolAddress((void**)&fH,  g_fH);
    cudaGetSymbolAddress((void**)&qpH, g_qkpH);
    cudaGetSymbolAddress((void**)&qkH, g_wqkvH);
    cudaGetSymbolAddress((void**)&woH, g_woH);
    cudaGetSymbolAddress((void**)&f1H, g_fc1H);
    cudaGetSymbolAddress((void**)&f2H, g_fc2H);
    cudaGetSymbolAddress((void**)&lmH, g_lmhH);

    cudaFuncSetAttribute((const void*)fattn2_kernel,              cudaFuncAttributeMaxDynamicSharedMemorySize, FA2_SMEM);
    cudaFuncSetAttribute((const void*)gemm_pk<2,0,false,2,false>, cudaFuncAttributeMaxDynamicSharedMemorySize, SMEM_NI2);
    cudaFuncSetAttribute((const void*)gemm_pk<0,0,false,2,false>, cudaFuncAttributeMaxDynamicSharedMemorySize, SMEM_NI2);
    cudaFuncSetAttribute((const void*)gemm_pk<1,2,false,4,false>, cudaFuncAttributeMaxDynamicSharedMemorySize, SMEM_NI4);
    cudaFuncSetAttribute((const void*)gemm_pk<0,1,false,2,false>, cudaFuncAttributeMaxDynamicSharedMemorySize, SMEM_NI2);
    cudaFuncSetAttribute((const void*)gemm_pk<0,0,true,4,true>,   cudaFuncAttributeMaxDynamicSharedMemorySize, SMEM_NI4);

    embed_kernel<<<BT_, 256>>>(ids, tok, pos);                           // 1
    prepack_qkvw<<<dim3(QKVW_/64, 8, L_), 256>>>(WQ, WK, WV);            // 2
    prepack_small<<<dim3(32, 32, 3*L_), 256>>>(WO, fc1w, fc2w);          // 3

    for (int l = 0; l < L_; l++) {
        // QKV: NTILE=64 -> 384 CTAs (better wave balance)
        gemm_pk<2,0,false,2,false><<<dim3(QKVW_/64, BT_/128), 256, SMEM_NI2>>>(
            BT_, QKVW_, D_, xH,
            qkH + (size_t)l*QKVW_*256,
            pv, 512, qpH, nullptr);                                      // 4 (l=0)

        fattn2_kernel<<<dim3(16, B_*H_), 128, FA2_SMEM>>>();             // 5 (l=0)

        gemm_pk<0,0,false,2,false><<<dim3(D_/64, BT_/128), 256, SMEM_NI2>>>(
            BT_, D_, D_, cH,
            woH + (size_t)l*D_*256,
            ptmp, D_, nullptr, nullptr);

        add_ln_kernel<<<BT_, 256>>>(ln1g + l*D_, ln1b + l*D_);

        gemm_pk<1,2,false,4,false><<<dim3(DFF_/128, BT_/128), 256, SMEM_NI4>>>(
            BT_, DFF_, D_, xH,
            f1H + (size_t)l*DFF_*256,
            nullptr, 0, fH, fc1b + l*DFF_);

        gemm_pk<0,1,false,2,false><<<dim3(D_/64, BT_/128), 256, SMEM_NI2>>>(
            BT_, D_, DFF_, fH,
            f2H + (size_t)l*D_*1024,
            ptmp, D_, nullptr, fc2b + l*D_);

        add_ln_kernel<<<BT_, 256>>>(ln2g + l*D_, ln2b + l*D_);
    }

    prepack_b_hi<<<dim3(VP_/64, 8), 256>>>(lmh, lmH, D_, V_, VP_);

    gemm_pk<0,0,true,4,true><<<dim3(BT_/128, VP_/128), 256, SMEM_NI4>>>(
        BT_, V_, D_, xH, lmH, out, V_, nullptr, nullptr);
}